// round 1
// baseline (speedup 1.0000x reference)
#include <cuda_runtime.h>
#include <math.h>

#define NSEG   2047
#define NPIX   16384      // 128*128
#define GRID_N 128
#define CH     128        // segments per chunk staged in smem
#define NCHUNK 16         // ceil(2047/128)
#define NBAND  16         // 16 bands of 8 rows
#define GAMMA_F 200.0f

// Per-segment SoA for both transforms (0 = pred, 1 = gt)
__device__ float g_pjx[2][NSEG];
__device__ float g_pjy[2][NSEG];
__device__ float g_vx [2][NSEG];
__device__ float g_vy [2][NSEG];
__device__ float g_inv[2][NSEG];

// Per-pixel min squared distance (as uint bits; d2 >= 0 so uint order == float order)
__device__ unsigned g_min[2][NPIX];

// ---------------------------------------------------------------------------
// init: set min arrays to +inf, zero the output scalar
// ---------------------------------------------------------------------------
__global__ void init_kernel(float* out) {
    int i = blockIdx.x * blockDim.x + threadIdx.x;
    if (i < 2 * NPIX) ((unsigned*)g_min)[i] = 0x7F800000u;  // +inf
    if (i == 0) out[0] = 0.0f;
}

// ---------------------------------------------------------------------------
// prep: build per-segment data. blockIdx.y = which transform.
// Segment s: pi = kps[s], pj = kps[s+1], v = pi - pj, masked iff mask[s].
// Masked -> pj pushed far away + inv = 0  => t = 0, diff = u (huge) => beta 0.
// ---------------------------------------------------------------------------
__global__ void prep_kernel(const float* __restrict__ pred,
                            const float* __restrict__ gt) {
    int s = blockIdx.x * blockDim.x + threadIdx.x;
    int w = blockIdx.y;
    if (s >= NSEG) return;
    const float* c = (w == 0) ? pred : gt;

    float pen_i = c[s * 3 + 2];
    bool masked = (w == 0) ? (pen_i > 0.5f) : (pen_i != 0.0f);

    if (masked) {
        g_pjx[w][s] = 1e18f;
        g_pjy[w][s] = 1e18f;
        g_vx [w][s] = 0.0f;
        g_vy [w][s] = 0.0f;
        g_inv[w][s] = 0.0f;
    } else {
        float pix = (c[s * 3 + 0]       - 0.5f) * 2.0f;
        float piy = (c[s * 3 + 1]       - 0.5f) * 2.0f;
        float pjx = (c[(s + 1) * 3 + 0] - 0.5f) * 2.0f;
        float pjy = (c[(s + 1) * 3 + 1] - 0.5f) * 2.0f;
        float vx = pix - pjx;
        float vy = piy - pjy;
        float vn = vx * vx + vy * vy;
        g_pjx[w][s] = pjx;
        g_pjy[w][s] = pjy;
        g_vx [w][s] = vx;
        g_vy [w][s] = vy;
        g_inv[w][s] = (vn == 0.0f) ? 0.0f : (1.0f / vn);
    }
}

// ---------------------------------------------------------------------------
// main: per-pixel min over a chunk of segments.
// grid = (NBAND, NCHUNK, 2), block = 128 threads.
// Each thread owns 8 contiguous pixels in ONE row (shared gy -> uy, uy*vy
// hoisted per segment). Band = 8 rows x 128 cols = 1024 px per CTA.
// ---------------------------------------------------------------------------
__global__ void __launch_bounds__(128) main_kernel() {
    const int which = blockIdx.z;
    const int band  = blockIdx.x;   // 0..15
    const int chunk = blockIdx.y;   // 0..15

    __shared__ float s_pjx[CH], s_pjy[CH], s_vx[CH], s_vy[CH], s_inv[CH];

    const int s0  = chunk * CH;
    const int cnt = (s0 + CH <= NSEG) ? CH : (NSEG - s0);
    for (int i = threadIdx.x; i < cnt; i += blockDim.x) {
        s_pjx[i] = g_pjx[which][s0 + i];
        s_pjy[i] = g_pjy[which][s0 + i];
        s_vx [i] = g_vx [which][s0 + i];
        s_vy [i] = g_vy [which][s0 + i];
        s_inv[i] = g_inv[which][s0 + i];
    }
    __syncthreads();

    const int t   = threadIdx.x;
    const int r   = t >> 4;            // 0..7  (row within band)
    const int c0  = (t & 15) * 8;      // 0..120 (first of 8 columns)
    const int row = band * 8 + r;
    const float step = 2.0f / 127.0f;
    const float gy = fmaf((float)row, step, -1.0f);

    float gx[8], m[8];
#pragma unroll
    for (int k = 0; k < 8; k++) {
        gx[k] = fmaf((float)(c0 + k), step, -1.0f);
        m[k]  = __int_as_float(0x7F800000);  // +inf
    }

#pragma unroll 2
    for (int i = 0; i < cnt; i++) {
        const float pjx = s_pjx[i];
        const float pjy = s_pjy[i];
        const float vx  = s_vx [i];
        const float vy  = s_vy [i];
        const float inv = s_inv[i];
        const float uy  = gy - pjy;
        const float uvy = uy * vy;
#pragma unroll
        for (int k = 0; k < 8; k++) {
            float ux = gx[k] - pjx;
            float uv = fmaf(ux, vx, uvy);
            float tt = fminf(fmaxf(uv * inv, 0.0f), 1.0f);
            float dx = fmaf(-tt, vx, ux);
            float dy = fmaf(-tt, vy, uy);
            float d2 = fmaf(dy, dy, dx * dx);
            m[k] = fminf(m[k], d2);
        }
    }

    unsigned* dst = g_min[which];
    const int pbase = row * GRID_N + c0;
#pragma unroll
    for (int k = 0; k < 8; k++)
        atomicMin(&dst[pbase + k], __float_as_uint(m[k]));
}

// ---------------------------------------------------------------------------
// reduce: beta = exp(-gamma * min_d2) for both, MSE over pixels.
// grid = 16, block = 1024 (16*1024 = 16384 pixels).
// ---------------------------------------------------------------------------
__global__ void reduce_kernel(float* __restrict__ out) {
    const int p = blockIdx.x * blockDim.x + threadIdx.x;
    float ep = expf(-GAMMA_F * __uint_as_float(g_min[0][p]));
    float eg = expf(-GAMMA_F * __uint_as_float(g_min[1][p]));
    float d  = ep - eg;
    float v  = d * d;

    // warp reduction
#pragma unroll
    for (int o = 16; o > 0; o >>= 1)
        v += __shfl_down_sync(0xFFFFFFFFu, v, o);

    __shared__ float ws[32];
    const int lane = threadIdx.x & 31;
    const int wid  = threadIdx.x >> 5;
    if (lane == 0) ws[wid] = v;
    __syncthreads();
    if (wid == 0) {
        float bv = (lane < (int)(blockDim.x >> 5)) ? ws[lane] : 0.0f;
#pragma unroll
        for (int o = 16; o > 0; o >>= 1)
            bv += __shfl_down_sync(0xFFFFFFFFu, bv, o);
        if (lane == 0)
            atomicAdd(out, bv * (1.0f / (float)NPIX));
    }
}

// ---------------------------------------------------------------------------
extern "C" void kernel_launch(void* const* d_in, const int* in_sizes, int n_in,
                              void* d_out, int out_size) {
    const float* pred = (const float*)d_in[0];
    const float* gt   = (const float*)d_in[1];
    float* out = (float*)d_out;

    init_kernel<<<(2 * NPIX + 1023) / 1024, 1024>>>(out);

    dim3 pgrid((NSEG + 127) / 128, 2, 1);
    prep_kernel<<<pgrid, 128>>>(pred, gt);

    dim3 mgrid(NBAND, NCHUNK, 2);
    main_kernel<<<mgrid, 128>>>();

    reduce_kernel<<<NPIX / 1024, 1024>>>(out);
}